// round 4
// baseline (speedup 1.0000x reference)
#include <cuda_runtime.h>

// Problem constants (fixed by the dataset)
#define N_BATCH 2
#define N_PLANES 3
#define C_CH 32
#define HW 65536          // 256*256
#define NRAYS 32768       // N_BATCH * 16384
#define S_DEPTH 32
#define RPB 4             // rays (warps) per block
#define THREADS 128

// channels-last copy of the planes: [(n*3+p)][hw][c]
__device__ float g_planesT[(size_t)N_BATCH * N_PLANES * HW * C_CH];

// ---------- packed f32x2 helpers (ptxas won't emit FFMA2 from C++) ----------
typedef unsigned long long u64;

__device__ __forceinline__ u64 ffma2(u64 a, u64 b, u64 c) {
    u64 r; asm("fma.rn.f32x2 %0,%1,%2,%3;" : "=l"(r) : "l"(a), "l"(b), "l"(c)); return r;
}
__device__ __forceinline__ u64 pack2(float lo, float hi) {
    u64 r; asm("mov.b64 %0,{%1,%2};" : "=l"(r) : "f"(lo), "f"(hi)); return r;
}
__device__ __forceinline__ void unpack2(u64 d, float& lo, float& hi) {
    asm("mov.b64 {%0,%1},%2;" : "=f"(lo), "=f"(hi) : "l"(d));
}
__device__ __forceinline__ float softplus_f(float x) {
    return fmaxf(x, 0.f) + __logf(1.f + __expf(-fabsf(x)));
}

// ---------- kernel 0: [np][C][HW] -> [np][HW][C] tiled transpose ----------
__global__ void transpose_kernel(const float* __restrict__ in) {
    __shared__ float tile[32][33];
    int np  = blockIdx.y;
    int hw0 = blockIdx.x * 32;
    int tx = threadIdx.x, ty = threadIdx.y;
#pragma unroll
    for (int i = 0; i < 4; i++) {
        int cc = ty * 4 + i;
        tile[cc][tx] = in[(np * 32 + cc) * HW + hw0 + tx];
    }
    __syncthreads();
#pragma unroll
    for (int i = 0; i < 4; i++) {
        int row = ty * 4 + i;
        g_planesT[(size_t)(np * HW + hw0 + row) * 32 + tx] = tile[tx][row];
    }
}

// ---------- kernel 1: full renderer, one warp per ray ----------
__global__ __launch_bounds__(THREADS) void render_kernel(
    const float* __restrict__ orig, const float* __restrict__ dirs,
    const float* __restrict__ w1, const float* __restrict__ b1,
    const float* __restrict__ w2, const float* __restrict__ b2,
    float* __restrict__ out)
{
    __shared__ __align__(16) float w1s[32 * 64];   // [c][j]
    __shared__ __align__(16) float b1s[64];
    __shared__ __align__(16) float w2rs[64 * 32];  // rgb columns, pair-aligned
    __shared__ float w2sigs[64];                   // sigma column
    __shared__ __align__(16) float b2rs[32];
    __shared__ float b2sigs;
    __shared__ int2  taps[RPB][32][12];            // (addr, weight-bits)
    __shared__ float feats[RPB][32 * 33];          // [s][c], pad 33

    const int tid = threadIdx.x;
    for (int i = tid; i < 32 * 64; i += THREADS) w1s[i] = w1[i];
    if (tid < 64) b1s[tid] = b1[tid];
    for (int i = tid; i < 64 * 33; i += THREADS) {
        int j = i / 33, k = i - j * 33;
        float v = w2[i];
        if (k == 0) w2sigs[j] = v; else w2rs[j * 32 + (k - 1)] = v;
    }
    if (tid < 32) b2rs[tid] = b2[tid + 1];
    if (tid == 0) b2sigs = b2[0];
    __syncthreads();

    const int w = tid >> 5, lane = tid & 31;
    const int rg = blockIdx.x * RPB + w;   // global ray id
    const int n  = rg >> 14;               // batch index

    const float ox = orig[rg * 3 + 0], oy = orig[rg * 3 + 1], oz = orig[rg * 3 + 2];
    const float dx = dirs[rg * 3 + 0], dy = dirs[rg * 3 + 1], dz = dirs[rg * 3 + 2];

    // ---- stage 1: thread = sample. Compute 12 (addr, weight) taps ----
    const float t   = (lane + 0.5f) * 0.03125f;
    const float dep = 2.25f + 1.05f * t;
    const float cx = 2.f * fmaf(dep, dx, ox);
    const float cy = 2.f * fmaf(dep, dy, oy);
    const float cz = 2.f * fmaf(dep, dz, oz);

#pragma unroll
    for (int p = 0; p < 3; p++) {
        float u = (p == 0) ? cx : (p == 1) ? cy : cx;
        float v = (p == 0) ? cy : (p == 1) ? cz : cz;
        float ix = ((u + 1.f) * 0.5f) * 255.f;
        float iy = ((v + 1.f) * 0.5f) * 255.f;
        float fx0 = floorf(ix), fy0 = floorf(iy);
        float a0 = ix - fx0, a1 = (fx0 + 1.f) - ix;   // match ref's unclamped weights
        float bb0 = iy - fy0, bb1 = (fy0 + 1.f) - iy;
        int ix0 = (int)fminf(fmaxf(fx0, 0.f), 255.f);
        int ix1 = (int)fminf(fmaxf(fx0 + 1.f, 0.f), 255.f);
        int iy0 = (int)fminf(fmaxf(fy0, 0.f), 255.f);
        int iy1 = (int)fminf(fmaxf(fy0 + 1.f, 0.f), 255.f);
        int base = (n * 3 + p) * (HW * 32);
        int r0 = base + iy0 * (256 * 32);
        int r1 = base + iy1 * (256 * 32);
        taps[w][lane][p * 4 + 0] = make_int2(r0 + ix0 * 32, __float_as_int(a1 * bb1));
        taps[w][lane][p * 4 + 1] = make_int2(r0 + ix1 * 32, __float_as_int(a0 * bb1));
        taps[w][lane][p * 4 + 2] = make_int2(r1 + ix0 * 32, __float_as_int(a1 * bb0));
        taps[w][lane][p * 4 + 3] = make_int2(r1 + ix1 * 32, __float_as_int(a0 * bb0));
    }
    __syncwarp();

    // ---- stage 2: lane = channel. Coalesced 128B gathers per tap ----
    {
        const int c = lane;
        for (int s = 0; s < 32; s++) {
            float ac0 = 0.f, ac1 = 0.f, ac2 = 0.f, ac3 = 0.f;
#pragma unroll
            for (int tp = 0; tp < 12; tp += 4) {
                int2 t0 = taps[w][s][tp + 0];
                int2 t1 = taps[w][s][tp + 1];
                int2 t2 = taps[w][s][tp + 2];
                int2 t3 = taps[w][s][tp + 3];
                ac0 = fmaf(__int_as_float(t0.y), __ldg(&g_planesT[t0.x + c]), ac0);
                ac1 = fmaf(__int_as_float(t1.y), __ldg(&g_planesT[t1.x + c]), ac1);
                ac2 = fmaf(__int_as_float(t2.y), __ldg(&g_planesT[t2.x + c]), ac2);
                ac3 = fmaf(__int_as_float(t3.y), __ldg(&g_planesT[t3.x + c]), ac3);
            }
            feats[w][s * 33 + c] = ((ac0 + ac1) + (ac2 + ac3)) * (1.f / 3.f);
        }
    }
    __syncwarp();

    // ---- phase B: thread = sample. MLP with packed f32x2 FFMA2 ----
    const float* frow = &feats[w][lane * 33];

    u64 acc[32];
    const u64* b1d = (const u64*)b1s;
#pragma unroll
    for (int jp = 0; jp < 32; jp++) acc[jp] = b1d[jp];

    const ulonglong2* w1d2 = (const ulonglong2*)w1s;
#pragma unroll 2
    for (int cc = 0; cc < 32; cc++) {
        float fc = frow[cc];
        u64 fc2 = pack2(fc, fc);
        const ulonglong2* wr = w1d2 + cc * 16;
#pragma unroll
        for (int jq = 0; jq < 16; jq++) {
            ulonglong2 ww = wr[jq];
            acc[2 * jq]     = ffma2(fc2, ww.x, acc[2 * jq]);
            acc[2 * jq + 1] = ffma2(fc2, ww.y, acc[2 * jq + 1]);
        }
    }
    float h[64];
#pragma unroll
    for (int jp = 0; jp < 32; jp++) {
        float lo, hi; unpack2(acc[jp], lo, hi);
        h[2 * jp]     = softplus_f(lo);
        h[2 * jp + 1] = softplus_f(hi);
    }

    u64 acc2[16];
    const u64* b2d = (const u64*)b2rs;
#pragma unroll
    for (int k = 0; k < 16; k++) acc2[k] = b2d[k];
    float sig = b2sigs;
    const ulonglong2* w2d2 = (const ulonglong2*)w2rs;
#pragma unroll 2
    for (int j = 0; j < 64; j++) {
        float hj = h[j];
        u64 hj2 = pack2(hj, hj);
        sig = fmaf(hj, w2sigs[j], sig);
        const ulonglong2* wr = w2d2 + j * 8;
#pragma unroll
        for (int kq = 0; kq < 8; kq++) {
            ulonglong2 ww = wr[kq];
            acc2[2 * kq]     = ffma2(hj2, ww.x, acc2[2 * kq]);
            acc2[2 * kq + 1] = ffma2(hj2, ww.y, acc2[2 * kq + 1]);
        }
    }

    float rgb[32];
#pragma unroll
    for (int k = 0; k < 16; k++) {
        float lo, hi; unpack2(acc2[k], lo, hi);
        rgb[2 * k]     = __fdividef(1.002f, 1.f + __expf(-lo)) - 0.001f;
        rgb[2 * k + 1] = __fdividef(1.002f, 1.f + __expf(-hi)) - 0.001f;
    }

    // ---- ray marching: warp scan over samples (lane = s) ----
    const unsigned FULL = 0xffffffffu;
    float sig_n = __shfl_down_sync(FULL, sig, 1);
    float dep_n = __shfl_down_sync(FULL, dep, 1);
    float alpha;
    if (lane < 31) {
        float delta = dep_n - dep;
        float dm = 0.5f * (sig + sig_n);
        float dens = softplus_f(dm - 1.f);
        alpha = 1.f - __expf(-delta * dens);
    } else {
        alpha = 0.f;
    }
    float g = 1.f - alpha + 1e-10f;
    float pscan = g;
#pragma unroll
    for (int off = 1; off < 32; off <<= 1) {
        float v = __shfl_up_sync(FULL, pscan, off);
        if (lane >= off) pscan *= v;
    }
    float T = __shfl_up_sync(FULL, pscan, 1);
    if (lane == 0) T = 1.f;
    float wgt = alpha * T;                      // weights[s], s<31 (lane31 -> 0)
    float wprev = __shfl_up_sync(FULL, wgt, 1);
    if (lane == 0) wprev = 0.f;
    float coeff = 0.5f * (wgt + wprev);         // contribution of rgb[s] to the sum

#pragma unroll
    for (int k = 0; k < 32; k++) rgb[k] *= coeff;
#pragma unroll
    for (int off = 16; off >= 1; off >>= 1) {
#pragma unroll
        for (int k = 0; k < 32; k++) rgb[k] += __shfl_xor_sync(FULL, rgb[k], off);
    }
    if (lane == 0) {
        float4* o4 = (float4*)(out + rg * 32);
#pragma unroll
        for (int k = 0; k < 8; k++)
            o4[k] = make_float4(rgb[4 * k], rgb[4 * k + 1], rgb[4 * k + 2], rgb[4 * k + 3]);
    }
}

extern "C" void kernel_launch(void* const* d_in, const int* in_sizes, int n_in,
                              void* d_out, int out_size) {
    const float* vol  = (const float*)d_in[0];  // [2,3,32,256,256]
    const float* orig = (const float*)d_in[1];  // [2,16384,3]
    const float* dirs = (const float*)d_in[2];  // [2,16384,3]
    const float* w1   = (const float*)d_in[3];  // [32,64]
    const float* b1   = (const float*)d_in[4];  // [64]
    const float* w2   = (const float*)d_in[5];  // [64,33]
    const float* b2   = (const float*)d_in[6];  // [33]
    float* out = (float*)d_out;

    dim3 tb(32, 8);
    dim3 tg(HW / 32, N_BATCH * N_PLANES);
    transpose_kernel<<<tg, tb>>>(vol);

    render_kernel<<<NRAYS / RPB, THREADS>>>(orig, dirs, w1, b1, w2, b2, out);
}

// round 5
// speedup vs baseline: 1.1610x; 1.1610x over previous
#include <cuda_runtime.h>

// Problem constants (fixed by the dataset)
#define N_BATCH 2
#define N_PLANES 3
#define C_CH 32
#define HW 65536          // 256*256
#define NRAYS 32768       // N_BATCH * 16384
#define S_DEPTH 32
#define RPB 4             // rays (warps) per block
#define THREADS 128

// channels-last copy of the planes: [(n*3+p)][hw][c]
__device__ float g_planesT[(size_t)N_BATCH * N_PLANES * HW * C_CH];

// ---------- packed f32x2 helpers (ptxas won't emit FFMA2 from C++) ----------
typedef unsigned long long u64;

__device__ __forceinline__ u64 ffma2(u64 a, u64 b, u64 c) {
    u64 r; asm("fma.rn.f32x2 %0,%1,%2,%3;" : "=l"(r) : "l"(a), "l"(b), "l"(c)); return r;
}
__device__ __forceinline__ u64 pack2(float lo, float hi) {
    u64 r; asm("mov.b64 %0,{%1,%2};" : "=l"(r) : "f"(lo), "f"(hi)); return r;
}
__device__ __forceinline__ void unpack2(u64 d, float& lo, float& hi) {
    asm("mov.b64 {%0,%1},%2;" : "=f"(lo), "=f"(hi) : "l"(d));
}
__device__ __forceinline__ float softplus_f(float x) {
    return fmaxf(x, 0.f) + __logf(1.f + __expf(-fabsf(x)));
}

// ---------- kernel 0: [np][C][HW] -> [np][HW][C] tiled transpose ----------
__global__ void transpose_kernel(const float* __restrict__ in) {
    __shared__ float tile[32][33];
    int np  = blockIdx.y;
    int hw0 = blockIdx.x * 32;
    int tx = threadIdx.x, ty = threadIdx.y;
#pragma unroll
    for (int i = 0; i < 4; i++) {
        int cc = ty * 4 + i;
        tile[cc][tx] = in[(np * 32 + cc) * HW + hw0 + tx];
    }
    __syncthreads();
#pragma unroll
    for (int i = 0; i < 4; i++) {
        int row = ty * 4 + i;
        g_planesT[(size_t)(np * HW + hw0 + row) * 32 + tx] = tile[tx][row];
    }
}

// ---------- kernel 1: full renderer, one warp per ray ----------
__global__ __launch_bounds__(THREADS, 4) void render_kernel(
    const float* __restrict__ orig, const float* __restrict__ dirs,
    const float* __restrict__ w1, const float* __restrict__ b1,
    const float* __restrict__ w2, const float* __restrict__ b2,
    float* __restrict__ out)
{
    __shared__ __align__(16) float w1s[32 * 64];   // [c][j]
    __shared__ __align__(16) float b1s[64];
    __shared__ __align__(16) float w2rs[64 * 32];  // rgb columns, pair-aligned
    __shared__ float w2sigs[64];                   // sigma column
    __shared__ __align__(16) float b2rs[32];
    __shared__ float b2sigs;
    __shared__ int2  taps[RPB][32][12];            // (addr, weight-bits)
    __shared__ float feats[RPB][32 * 33];          // [s][c], pad 33

    const int tid = threadIdx.x;
    for (int i = tid; i < 32 * 64; i += THREADS) w1s[i] = w1[i];
    if (tid < 64) b1s[tid] = b1[tid];
    for (int i = tid; i < 64 * 33; i += THREADS) {
        int j = i / 33, k = i - j * 33;
        float v = w2[i];
        if (k == 0) w2sigs[j] = v; else w2rs[j * 32 + (k - 1)] = v;
    }
    if (tid < 32) b2rs[tid] = b2[tid + 1];
    if (tid == 0) b2sigs = b2[0];
    __syncthreads();

    const int w = tid >> 5, lane = tid & 31;
    const int rg = blockIdx.x * RPB + w;   // global ray id
    const int n  = rg >> 14;               // batch index

    const float ox = orig[rg * 3 + 0], oy = orig[rg * 3 + 1], oz = orig[rg * 3 + 2];
    const float dx = dirs[rg * 3 + 0], dy = dirs[rg * 3 + 1], dz = dirs[rg * 3 + 2];

    // ---- stage 1: thread = sample. Compute 12 (addr, weight) taps ----
    const float t   = (lane + 0.5f) * 0.03125f;
    const float dep = 2.25f + 1.05f * t;
    const float cx = 2.f * fmaf(dep, dx, ox);
    const float cy = 2.f * fmaf(dep, dy, oy);
    const float cz = 2.f * fmaf(dep, dz, oz);

#pragma unroll
    for (int p = 0; p < 3; p++) {
        float u = (p == 0) ? cx : (p == 1) ? cy : cx;
        float v = (p == 0) ? cy : (p == 1) ? cz : cz;
        float ix = ((u + 1.f) * 0.5f) * 255.f;
        float iy = ((v + 1.f) * 0.5f) * 255.f;
        float fx0 = floorf(ix), fy0 = floorf(iy);
        float a0 = ix - fx0, a1 = (fx0 + 1.f) - ix;   // match ref's unclamped weights
        float bb0 = iy - fy0, bb1 = (fy0 + 1.f) - iy;
        int ix0 = (int)fminf(fmaxf(fx0, 0.f), 255.f);
        int ix1 = (int)fminf(fmaxf(fx0 + 1.f, 0.f), 255.f);
        int iy0 = (int)fminf(fmaxf(fy0, 0.f), 255.f);
        int iy1 = (int)fminf(fmaxf(fy0 + 1.f, 0.f), 255.f);
        int base = (n * 3 + p) * (HW * 32);
        int r0 = base + iy0 * (256 * 32);
        int r1 = base + iy1 * (256 * 32);
        taps[w][lane][p * 4 + 0] = make_int2(r0 + ix0 * 32, __float_as_int(a1 * bb1));
        taps[w][lane][p * 4 + 1] = make_int2(r0 + ix1 * 32, __float_as_int(a0 * bb1));
        taps[w][lane][p * 4 + 2] = make_int2(r1 + ix0 * 32, __float_as_int(a1 * bb0));
        taps[w][lane][p * 4 + 3] = make_int2(r1 + ix1 * 32, __float_as_int(a0 * bb0));
    }
    __syncwarp();

    // ---- stage 2: vectorized gather. 4 tap-groups x 8 channel-lanes.
    //      Each lane loads float4 (4 channels) for its tap group: 3 LDG.128/sample.
    {
        const int g    = lane >> 3;          // tap group 0..3
        const int cpos = (lane & 7) * 4;     // channel base within float4
        const int cstore = cpos + g;         // channel this lane stores after reduce
        const unsigned FULL = 0xffffffffu;
#pragma unroll 4
        for (int s = 0; s < 32; s++) {
            float a0 = 0.f, a1 = 0.f, a2 = 0.f, a3 = 0.f;
#pragma unroll
            for (int r = 0; r < 3; r++) {
                int2 tw = taps[w][s][r * 4 + g];
                float wt = __int_as_float(tw.y);
                const float4 v = *(const float4*)&g_planesT[tw.x + cpos];
                a0 = fmaf(wt, v.x, a0);
                a1 = fmaf(wt, v.y, a1);
                a2 = fmaf(wt, v.z, a2);
                a3 = fmaf(wt, v.w, a3);
            }
            // reduce across the 4 tap groups (lanes xor 8, 16)
#pragma unroll
            for (int off = 8; off <= 16; off <<= 1) {
                a0 += __shfl_xor_sync(FULL, a0, off);
                a1 += __shfl_xor_sync(FULL, a1, off);
                a2 += __shfl_xor_sync(FULL, a2, off);
                a3 += __shfl_xor_sync(FULL, a3, off);
            }
            float val = (g == 0) ? a0 : (g == 1) ? a1 : (g == 2) ? a2 : a3;
            feats[w][s * 33 + cstore] = val * (1.f / 3.f);
        }
    }
    __syncwarp();

    // ---- phase B: thread = sample. MLP, split into two 32-hidden halves to
    //      keep register pressure low; packed f32x2 FFMA2 throughout.
    const float* frow = &feats[w][lane * 33];

    float sig = b2sigs;
    u64 acc2[16];
    const u64* b2d = (const u64*)b2rs;
#pragma unroll
    for (int k = 0; k < 16; k++) acc2[k] = b2d[k];

    const ulonglong2* w1d2 = (const ulonglong2*)w1s;
    const ulonglong2* w2d2 = (const ulonglong2*)w2rs;
    const u64* b1d = (const u64*)b1s;

#pragma unroll
    for (int half = 0; half < 2; half++) {
        u64 acc[16];
#pragma unroll
        for (int jp = 0; jp < 16; jp++) acc[jp] = b1d[half * 16 + jp];

#pragma unroll 4
        for (int cc = 0; cc < 32; cc++) {
            float fc = frow[cc];
            u64 fc2 = pack2(fc, fc);
            const ulonglong2* wr = w1d2 + cc * 16 + half * 8;
#pragma unroll
            for (int jq = 0; jq < 8; jq++) {
                ulonglong2 ww = wr[jq];
                acc[2 * jq]     = ffma2(fc2, ww.x, acc[2 * jq]);
                acc[2 * jq + 1] = ffma2(fc2, ww.y, acc[2 * jq + 1]);
            }
        }
        // consume these 32 hidden units into layer 2 immediately
#pragma unroll 4
        for (int jp = 0; jp < 16; jp++) {
            float lo, hi; unpack2(acc[jp], lo, hi);
            int j0 = half * 32 + 2 * jp;
            float h0 = softplus_f(lo);
            float h1 = softplus_f(hi);
            sig = fmaf(h0, w2sigs[j0], sig);
            sig = fmaf(h1, w2sigs[j0 + 1], sig);
            u64 h02 = pack2(h0, h0);
            u64 h12 = pack2(h1, h1);
            const ulonglong2* wr0 = w2d2 + j0 * 8;
#pragma unroll
            for (int kq = 0; kq < 8; kq++) {
                ulonglong2 ww0 = wr0[kq];
                ulonglong2 ww1 = wr0[8 + kq];
                u64 v0 = ffma2(h02, ww0.x, acc2[2 * kq]);
                u64 v1 = ffma2(h02, ww0.y, acc2[2 * kq + 1]);
                acc2[2 * kq]     = ffma2(h12, ww1.x, v0);
                acc2[2 * kq + 1] = ffma2(h12, ww1.y, v1);
            }
        }
    }

    float rgb[32];
#pragma unroll
    for (int k = 0; k < 16; k++) {
        float lo, hi; unpack2(acc2[k], lo, hi);
        rgb[2 * k]     = __fdividef(1.002f, 1.f + __expf(-lo)) - 0.001f;
        rgb[2 * k + 1] = __fdividef(1.002f, 1.f + __expf(-hi)) - 0.001f;
    }

    // ---- ray marching: warp scan over samples (lane = s) ----
    const unsigned FULL = 0xffffffffu;
    float sig_n = __shfl_down_sync(FULL, sig, 1);
    float dep_n = __shfl_down_sync(FULL, dep, 1);
    float alpha;
    if (lane < 31) {
        float delta = dep_n - dep;
        float dm = 0.5f * (sig + sig_n);
        float dens = softplus_f(dm - 1.f);
        alpha = 1.f - __expf(-delta * dens);
    } else {
        alpha = 0.f;
    }
    float gg = 1.f - alpha + 1e-10f;
    float pscan = gg;
#pragma unroll
    for (int off = 1; off < 32; off <<= 1) {
        float v = __shfl_up_sync(FULL, pscan, off);
        if (lane >= off) pscan *= v;
    }
    float T = __shfl_up_sync(FULL, pscan, 1);
    if (lane == 0) T = 1.f;
    float wgt = alpha * T;                      // weights[s], s<31 (lane31 -> 0)
    float wprev = __shfl_up_sync(FULL, wgt, 1);
    if (lane == 0) wprev = 0.f;
    float coeff = 0.5f * (wgt + wprev);         // contribution of rgb[s] to the sum

#pragma unroll
    for (int k = 0; k < 32; k++) rgb[k] *= coeff;
#pragma unroll
    for (int off = 16; off >= 1; off >>= 1) {
#pragma unroll
        for (int k = 0; k < 32; k++) rgb[k] += __shfl_xor_sync(FULL, rgb[k], off);
    }
    if (lane == 0) {
        float4* o4 = (float4*)(out + rg * 32);
#pragma unroll
        for (int k = 0; k < 8; k++)
            o4[k] = make_float4(rgb[4 * k], rgb[4 * k + 1], rgb[4 * k + 2], rgb[4 * k + 3]);
    }
}

extern "C" void kernel_launch(void* const* d_in, const int* in_sizes, int n_in,
                              void* d_out, int out_size) {
    const float* vol  = (const float*)d_in[0];  // [2,3,32,256,256]
    const float* orig = (const float*)d_in[1];  // [2,16384,3]
    const float* dirs = (const float*)d_in[2];  // [2,16384,3]
    const float* w1   = (const float*)d_in[3];  // [32,64]
    const float* b1   = (const float*)d_in[4];  // [64]
    const float* w2   = (const float*)d_in[5];  // [64,33]
    const float* b2   = (const float*)d_in[6];  // [33]
    float* out = (float*)d_out;

    dim3 tb(32, 8);
    dim3 tg(HW / 32, N_BATCH * N_PLANES);
    transpose_kernel<<<tg, tb>>>(vol);

    render_kernel<<<NRAYS / RPB, THREADS>>>(orig, dirs, w1, b1, w2, b2, out);
}